// round 13
// baseline (speedup 1.0000x reference)
#include <cuda_runtime.h>
#include <math.h>

#define HID     256
#define SLOTS   64
#define NB      4
#define TSTEPS  256
#define BATCH   512
#define KSM     192          // k-columns of W held in SMEM; k in [192,256) via LDG
#define NTH     256
#define EPSV    1e-5f

// Slot-memory scratch: 512 x 64 x 256 fp32 = 32 MB (L2-resident)
__device__ float g_mem[(size_t)BATCH * SLOTS * HID];

__device__ __forceinline__ float fast_tanh(float x) {
    float e = __expf(2.0f * x);
    return 1.0f - __fdividef(2.0f, e + 1.0f);
}

#define FFMA2(acc, a, b) \
    asm("fma.rn.f32x2 %0, %1, %2, %0;" : "+l"(acc) : "l"(a), "l"(b))

__global__ void __launch_bounds__(NTH, 1)
postnorm_rnn_kernel(const float* __restrict__ x,        // [512,256,1]
                    const float* __restrict__ W_embed,  // [256]
                    const float* __restrict__ b_embed,  // [256]
                    const float* __restrict__ W_update, // [256,256]
                    const float* __restrict__ b_update, // [256]
                    const float* __restrict__ gamma,    // [256]
                    const float* __restrict__ beta,     // [256]
                    const float* __restrict__ W_out,    // [10,256]
                    const float* __restrict__ b_out,    // [10]
                    const float* __restrict__ cs_in,    // [1]
                    float* __restrict__ out)            // [512,10]
{
    extern __shared__ float smem[];
    float* sW   = smem;                          // 256 rows x 192 cols = 49152 f
    float* vrow = sW + HID * KSM;                // [b][j] 4*256  =  1024 f
    float* xsm  = vrow + NB * HID;               // [b][t] 4*256  =  1024 f
    float* wtab = xsm + NB * TSTEPS;             // 64*5          =   320 f
    float* stab = wtab + 320;                    // 64 transition S values
    float* red  = stab + 64;                     // 8 warps x 8   =    64 f
    float* osm  = red + 64;                      // 160*4         =   640 f

    const int tid  = threadIdx.x;
    const int i    = tid;                 // hidden index owned (phase1/LN/mem)
    const int b0   = blockIdx.x * NB;
    const int warp = tid >> 5;
    const int lane = tid & 31;
    const int s    = tid & 7;             // k-slice id (8 slices of 32 k)
    const int rb   = tid & ~7;            // row block: rows rb..rb+7
    const int sK   = s * 4;               // k offset within each 32-float group

    // ---- zero this CTA's slot-memory slice ----
    {
        float4* mz = (float4*)(g_mem + (size_t)b0 * SLOTS * HID);
        for (int k = tid; k < NB * SLOTS * HID / 4; k += NTH)
            mz[k] = make_float4(0.f, 0.f, 0.f, 0.f);
    }
    // ---- stage W_update[:, 0:192] into SMEM (row-major, stride 192) ----
    {
        for (int idx = tid; idx < HID * (KSM / 4); idx += NTH) {
            int r = idx / (KSM / 4);           // 48 float4 per row
            int c = idx % (KSM / 4);
            ((float4*)(sW + r * KSM))[c] =
                ((const float4*)(W_update + (size_t)r * HID))[c];
        }
    }
    // ---- stage x: xsm[b][t] ----
    {
        int b = tid >> 6, t4 = tid & 63;
        ((float4*)xsm)[tid] =
            ((const float4*)(x + (size_t)(b0 + b) * TSTEPS))[t4];
    }
    // ---- precompute softmax weights + transition scalars S[base] ----
    if (tid < SLOTS) {
        int base = tid;
        float e[5], sum = 0.f, ep[5], sump = 0.f;
        int basep = (base + 1) & (SLOTS - 1);
#pragma unroll
        for (int k = 0; k < 5; k++) {
            int ix  = (base  + k - 2 + SLOTS) & (SLOTS - 1);
            int ixp = (basep + k - 2 + SLOTS) & (SLOTS - 1);
            float d  = (float)(ix  - base);
            float dp = (float)(ixp - basep);
            e[k]  = expf(-0.125f * d * d);   sum  += e[k];
            ep[k] = expf(-0.125f * dp * dp); sump += ep[k];
        }
        float inv = 1.0f / sum, invp = 1.0f / sump;
        float S = 0.f;
#pragma unroll
        for (int k = 0; k < 5; k++) {
            wtab[base * 5 + k] = e[k] * inv;
            if (k < 4) S += (ep[k] * invp) * (e[k + 1] * inv);
        }
        stab[base] = S;   // Sigma wn'(k) * wn(k+1), window-shift coupling
    }

    const float cs   = 1.0f / (1.0f + expf(-cs_in[0]));
    const float We_i = W_embed[i];
    const float be_i = b_embed[i];
    const float bu_i = b_update[i];
    const float g_i  = gamma[i];
    const float bt_i = beta[i];

    float h[NB];
    float m[NB][5];
    float* col[NB];
#pragma unroll
    for (int b = 0; b < NB; b++) {
        h[b] = 0.f;
        col[b] = g_mem + (size_t)(b0 + b) * SLOTS * HID + i;
#pragma unroll
        for (int k = 0; k < 5; k++) m[b][k] = 0.f;
    }

    const float* wsm = sW + rb * KSM + sK;                      // smem W, k<192
    const float* wgl = W_update + (size_t)rb * HID + sK;        // gmem W, k>=192
    const float* vbase = vrow + sK;

    __syncthreads();   // init visible

    // ---- vrow(0): ctx = 0, h = 0 -> v = tanh(x0*We+be) ----
#pragma unroll
    for (int b = 0; b < NB; b++)
        vrow[b * HID + i] = fast_tanh(fmaf(xsm[b * TSTEPS], We_i, be_i));
    __syncthreads();

    for (int t = 0; t < TSTEPS; t++) {
        const int base  = t & (SLOTS - 1);
        const int s_in  = ((base + 3)  & (SLOTS - 1)) * HID;
        const int s_out = ((base + 62) & (SLOTS - 1)) * HID;

        float pf[NB];
#pragma unroll
        for (int b = 0; b < NB; b++) pf[b] = col[b][s_in];

        float wn[5];
#pragma unroll
        for (int k = 0; k < 5; k++) wn[k] = wtab[base * 5 + k];

        // ---- phase 2: rows rb..rb+7 x 4 batches over k-slice {32jj + 4s + e}
        //      LDG tail (k>=192) issued FIRST so L2 latency overlaps smem work ----
        unsigned long long acc[8][4];
#pragma unroll
        for (int r = 0; r < 8; r++)
#pragma unroll
            for (int b = 0; b < 4; b++) acc[r][b] = 0ull;

#pragma unroll
        for (int jj = 6; jj < 8; jj++) {        // k in [192,256): uniform LDG
            const int off = jj * 32;
            ulonglong2 v0 = *(const ulonglong2*)(vbase + 0 * HID + off);
            ulonglong2 v1 = *(const ulonglong2*)(vbase + 1 * HID + off);
            ulonglong2 v2 = *(const ulonglong2*)(vbase + 2 * HID + off);
            ulonglong2 v3 = *(const ulonglong2*)(vbase + 3 * HID + off);
#pragma unroll
            for (int r = 0; r < 8; r++) {
                ulonglong2 w2 = __ldg((const ulonglong2*)(wgl + r * HID + off));
                FFMA2(acc[r][0], w2.x, v0.x); FFMA2(acc[r][0], w2.y, v0.y);
                FFMA2(acc[r][1], w2.x, v1.x); FFMA2(acc[r][1], w2.y, v1.y);
                FFMA2(acc[r][2], w2.x, v2.x); FFMA2(acc[r][2], w2.y, v2.y);
                FFMA2(acc[r][3], w2.x, v3.x); FFMA2(acc[r][3], w2.y, v3.y);
            }
        }
#pragma unroll
        for (int jj = 0; jj < 6; jj++) {        // k in [0,192): SMEM
            const int off = jj * 32;
            ulonglong2 v0 = *(const ulonglong2*)(vbase + 0 * HID + off);
            ulonglong2 v1 = *(const ulonglong2*)(vbase + 1 * HID + off);
            ulonglong2 v2 = *(const ulonglong2*)(vbase + 2 * HID + off);
            ulonglong2 v3 = *(const ulonglong2*)(vbase + 3 * HID + off);
#pragma unroll
            for (int r = 0; r < 8; r++) {
                ulonglong2 w2 = *(const ulonglong2*)(wsm + r * KSM + off);
                FFMA2(acc[r][0], w2.x, v0.x); FFMA2(acc[r][0], w2.y, v0.y);
                FFMA2(acc[r][1], w2.x, v1.x); FFMA2(acc[r][1], w2.y, v1.y);
                FFMA2(acc[r][2], w2.x, v2.x); FFMA2(acc[r][2], w2.y, v2.y);
                FFMA2(acc[r][3], w2.x, v3.x); FFMA2(acc[r][3], w2.y, v3.y);
            }
        }

        // ---- unpack partials ----
        float P[8][4];
#pragma unroll
        for (int r = 0; r < 8; r++)
#pragma unroll
            for (int b = 0; b < 4; b++) {
                float lo = __uint_as_float((unsigned)(acc[r][b] & 0xffffffffu));
                float hi = __uint_as_float((unsigned)(acc[r][b] >> 32));
                P[r][b] = lo + hi;
            }

        // ---- next-step prep (independent; fills shuffle latency below) ----
        const int  tn = (t + 1) & (TSTEPS - 1);
        const int  basep = (t + 1) & (SLOTS - 1);
        const float Bc = fmaf(cs, stab[base], 1.0f);
        float wnp[5];
#pragma unroll
        for (int k = 0; k < 5; k++) wnp[k] = wtab[basep * 5 + k];
        float A[NB];
#pragma unroll
        for (int b = 0; b < NB; b++) {
            float pre = wnp[4] * pf[b];
#pragma unroll
            for (int k = 0; k < 4; k++) pre = fmaf(wnp[k], m[b][k + 1], pre);
            float embp = fast_tanh(fmaf(xsm[b * TSTEPS + tn], We_i, be_i));
            A[b] = fmaf(cs, pre, embp);
        }

        // ---- routed butterfly over 8 k-slices: lane ends with row rb+s ----
        const bool h4 = (s & 4), h2 = (s & 2), h1 = (s & 1);
        float Q[4][4];
#pragma unroll
        for (int r = 0; r < 4; r++)
#pragma unroll
            for (int b = 0; b < 4; b++) {
                float keep = h4 ? P[r + 4][b] : P[r][b];
                float send = h4 ? P[r][b]     : P[r + 4][b];
                Q[r][b] = keep + __shfl_xor_sync(0xffffffffu, send, 4);
            }
        float R2[2][4];
#pragma unroll
        for (int r = 0; r < 2; r++)
#pragma unroll
            for (int b = 0; b < 4; b++) {
                float keep = h2 ? Q[r + 2][b] : Q[r][b];
                float send = h2 ? Q[r][b]     : Q[r + 2][b];
                R2[r][b] = keep + __shfl_xor_sync(0xffffffffu, send, 2);
            }
        float hn[NB];
#pragma unroll
        for (int b = 0; b < 4; b++) {
            float keep = h1 ? R2[1][b] : R2[0][b];
            float send = h1 ? R2[0][b] : R2[1][b];
            float u = keep + __shfl_xor_sync(0xffffffffu, send, 1);
            hn[b] = fast_tanh(u + bu_i);
        }

        // ---- LayerNorm reductions: (sum, sumsq) x 4 batches ----
        float r8[8];
#pragma unroll
        for (int b = 0; b < NB; b++) { r8[b] = hn[b]; r8[4 + b] = hn[b] * hn[b]; }
#pragma unroll
        for (int o = 16; o > 0; o >>= 1)
#pragma unroll
            for (int q = 0; q < 8; q++)
                r8[q] += __shfl_xor_sync(0xffffffffu, r8[q], o);
        if (lane == 0) {
#pragma unroll
            for (int q = 0; q < 8; q++) red[warp * 8 + q] = r8[q];
        }
        __syncthreads();   // bar2: red visible; all vrow(t) reads complete

        float4 S1 = make_float4(0.f, 0.f, 0.f, 0.f);
        float4 S2 = make_float4(0.f, 0.f, 0.f, 0.f);
#pragma unroll
        for (int w = 0; w < 8; w++) {
            float4 a4 = *(const float4*)(red + w * 8);
            float4 c4 = *(const float4*)(red + w * 8 + 4);
            S1.x += a4.x; S1.y += a4.y; S1.z += a4.z; S1.w += a4.w;
            S2.x += c4.x; S2.y += c4.y; S2.z += c4.z; S2.w += c4.w;
        }
        float s1a[4] = {S1.x, S1.y, S1.z, S1.w};
        float s2a[4] = {S2.x, S2.y, S2.z, S2.w};

        // ---- critical tail: hb -> one FMA -> STS ----
        float hb[NB];
#pragma unroll
        for (int b = 0; b < NB; b++) {
            float mu  = s1a[b] * (1.0f / HID);
            float var = fmaf(s2a[b], 1.0f / HID, -mu * mu);
            hb[b] = (hn[b] - mu) * rsqrtf(var + EPSV) * g_i + bt_i;
            vrow[b * HID + i] = fmaf(Bc, hb[b], A[b]);   // v(t+1)
        }
        __syncthreads();   // bar1: vrow(t+1) visible for next phase-2

        // ---- off-path: slot flush + window shift ----
#pragma unroll
        for (int b = 0; b < NB; b++) {
            h[b] = hb[b];
            col[b][s_out] = fmaf(wn[0], hb[b], m[b][0]);
            m[b][0] = fmaf(wn[1], hb[b], m[b][1]);
            m[b][1] = fmaf(wn[2], hb[b], m[b][2]);
            m[b][2] = fmaf(wn[3], hb[b], m[b][3]);
            m[b][3] = fmaf(wn[4], hb[b], m[b][4]);
            m[b][4] = pf[b];
        }
    }

    // ---- output: out[b,:] = h[b] @ W_out^T + b_out ----
    __syncthreads();
#pragma unroll
    for (int b = 0; b < NB; b++) vrow[b * HID + i] = h[b];
    __syncthreads();
    if (tid < 160) {                       // 16 segments x 10 outputs
        int o = tid % 10, seg = tid / 10;
        float a0 = 0.f, a1 = 0.f, a2 = 0.f, a3 = 0.f;
#pragma unroll
        for (int jj = 0; jj < 16; jj++) {
            int ii = seg * 16 + jj;
            float w = W_out[o * HID + ii];
            a0 = fmaf(w, vrow[0 * HID + ii], a0);
            a1 = fmaf(w, vrow[1 * HID + ii], a1);
            a2 = fmaf(w, vrow[2 * HID + ii], a2);
            a3 = fmaf(w, vrow[3 * HID + ii], a3);
        }
        osm[tid * 4 + 0] = a0; osm[tid * 4 + 1] = a1;
        osm[tid * 4 + 2] = a2; osm[tid * 4 + 3] = a3;
    }
    __syncthreads();
    if (tid < NB * 10) {
        int o = tid % 10, b = tid / 10;
        float sum = b_out[o];
#pragma unroll
        for (int seg = 0; seg < 16; seg++)
            sum += osm[(seg * 10 + o) * 4 + b];
        out[(size_t)(b0 + b) * 10 + o] = sum;
    }
}

extern "C" void kernel_launch(void* const* d_in, const int* in_sizes, int n_in,
                              void* d_out, int out_size) {
    (void)in_sizes; (void)n_in; (void)out_size;
    const float* x        = (const float*)d_in[0];
    const float* W_embed  = (const float*)d_in[1];
    const float* b_embed  = (const float*)d_in[2];
    const float* W_update = (const float*)d_in[3];
    const float* b_update = (const float*)d_in[4];
    const float* gamma    = (const float*)d_in[5];
    const float* beta     = (const float*)d_in[6];
    const float* W_out    = (const float*)d_in[7];
    const float* b_out    = (const float*)d_in[8];
    const float* cs       = (const float*)d_in[9];

    const size_t SMEM_BYTES =
        (size_t)(HID * KSM + NB * HID + NB * TSTEPS + 320 + 64 + 64 + 640)
        * sizeof(float);   // 209,152 B

    cudaFuncSetAttribute(postnorm_rnn_kernel,
                         cudaFuncAttributeMaxDynamicSharedMemorySize,
                         (int)SMEM_BYTES);

    postnorm_rnn_kernel<<<BATCH / NB, NTH, SMEM_BYTES>>>(
        x, W_embed, b_embed, W_update, b_update, gamma, beta,
        W_out, b_out, cs, (float*)d_out);
}

// round 14
// speedup vs baseline: 1.2929x; 1.2929x over previous
#include <cuda_runtime.h>
#include <math.h>

#define HID     256
#define SLOTS   64
#define NB      4
#define TSTEPS  256
#define BATCH   512
#define KSM     192          // k-columns of W in SMEM; k in [192,256) in REGISTERS
#define NTH     256
#define EPSV    1e-5f

// Slot-memory scratch: 512 x 64 x 256 fp32 = 32 MB (L2-resident)
__device__ float g_mem[(size_t)BATCH * SLOTS * HID];

__device__ __forceinline__ float fast_tanh(float x) {
    float e = __expf(2.0f * x);
    return 1.0f - __fdividef(2.0f, e + 1.0f);
}

#define FFMA2(acc, a, b) \
    asm("fma.rn.f32x2 %0, %1, %2, %0;" : "+l"(acc) : "l"(a), "l"(b))

__global__ void __launch_bounds__(NTH, 1)
postnorm_rnn_kernel(const float* __restrict__ x,        // [512,256,1]
                    const float* __restrict__ W_embed,  // [256]
                    const float* __restrict__ b_embed,  // [256]
                    const float* __restrict__ W_update, // [256,256]
                    const float* __restrict__ b_update, // [256]
                    const float* __restrict__ gamma,    // [256]
                    const float* __restrict__ beta,     // [256]
                    const float* __restrict__ W_out,    // [10,256]
                    const float* __restrict__ b_out,    // [10]
                    const float* __restrict__ cs_in,    // [1]
                    float* __restrict__ out)            // [512,10]
{
    extern __shared__ float smem[];
    float* sW   = smem;                          // 256 rows x 192 cols = 49152 f
    float* vrow = sW + HID * KSM;                // [b][j] 4*256  =  1024 f
    float* xsm  = vrow + NB * HID;               // [b][t] 4*256  =  1024 f
    float* wtab = xsm + NB * TSTEPS;             // 64*5          =   320 f
    float* stab = wtab + 320;                    // 64 transition S values
    float* red  = stab + 64;                     // 8 warps x 8   =    64 f
    float* osm  = red + 64;                      // 160*4         =   640 f

    const int tid  = threadIdx.x;
    const int i    = tid;                 // hidden index owned (phase1/LN/mem)
    const int b0   = blockIdx.x * NB;
    const int warp = tid >> 5;
    const int lane = tid & 31;
    const int s    = tid & 7;             // k-slice id (8 slices of 32 k)
    const int rb   = tid & ~7;            // row block: rows rb..rb+7
    const int sK   = s * 4;               // k offset within each 32-float group

    // ---- zero this CTA's slot-memory slice ----
    {
        float4* mz = (float4*)(g_mem + (size_t)b0 * SLOTS * HID);
        for (int k = tid; k < NB * SLOTS * HID / 4; k += NTH)
            mz[k] = make_float4(0.f, 0.f, 0.f, 0.f);
    }
    // ---- stage W_update[:, 0:192] into SMEM (row-major, stride 192) ----
    {
        for (int idx = tid; idx < HID * (KSM / 4); idx += NTH) {
            int r = idx / (KSM / 4);           // 48 float4 per row
            int c = idx % (KSM / 4);
            ((float4*)(sW + r * KSM))[c] =
                ((const float4*)(W_update + (size_t)r * HID))[c];
        }
    }
    // ---- stage x: xsm[b][t] ----
    {
        int b = tid >> 6, t4 = tid & 63;
        ((float4*)xsm)[tid] =
            ((const float4*)(x + (size_t)(b0 + b) * TSTEPS))[t4];
    }
    // ---- precompute softmax weights + transition scalars S[base] ----
    if (tid < SLOTS) {
        int base = tid;
        float e[5], sum = 0.f, ep[5], sump = 0.f;
        int basep = (base + 1) & (SLOTS - 1);
#pragma unroll
        for (int k = 0; k < 5; k++) {
            int ix  = (base  + k - 2 + SLOTS) & (SLOTS - 1);
            int ixp = (basep + k - 2 + SLOTS) & (SLOTS - 1);
            float d  = (float)(ix  - base);
            float dp = (float)(ixp - basep);
            e[k]  = expf(-0.125f * d * d);   sum  += e[k];
            ep[k] = expf(-0.125f * dp * dp); sump += ep[k];
        }
        float inv = 1.0f / sum, invp = 1.0f / sump;
        float S = 0.f;
#pragma unroll
        for (int k = 0; k < 5; k++) {
            wtab[base * 5 + k] = e[k] * inv;
            if (k < 4) S += (ep[k] * invp) * (e[k + 1] * inv);
        }
        stab[base] = S;   // Sigma wn'(k) * wn(k+1), window-shift coupling
    }

    const float cs   = 1.0f / (1.0f + expf(-cs_in[0]));
    const float We_i = W_embed[i];
    const float be_i = b_embed[i];
    const float bu_i = b_update[i];
    const float g_i  = gamma[i];
    const float bt_i = beta[i];

    float h[NB];
    float m[NB][5];
    float* col[NB];
#pragma unroll
    for (int b = 0; b < NB; b++) {
        h[b] = 0.f;
        col[b] = g_mem + (size_t)(b0 + b) * SLOTS * HID + i;
#pragma unroll
        for (int k = 0; k < 5; k++) m[b][k] = 0.f;
    }

    // ---- hoist W k-tail (k in [192,256), jj=6,7) into REGISTERS, once ----
    ulonglong2 wr[2][8];
#pragma unroll
    for (int jj = 0; jj < 2; jj++)
#pragma unroll
        for (int r = 0; r < 8; r++)
            wr[jj][r] = __ldg((const ulonglong2*)
                (W_update + (size_t)(rb + r) * HID + (192 + jj * 32) + sK));

    const float* wsm   = sW + rb * KSM + sK;     // smem W, k<192
    const float* vbase = vrow + sK;

    __syncthreads();   // init visible

    // ---- vrow(0): ctx = 0, h = 0 -> v = tanh(x0*We+be) ----
#pragma unroll
    for (int b = 0; b < NB; b++)
        vrow[b * HID + i] = fast_tanh(fmaf(xsm[b * TSTEPS], We_i, be_i));
    __syncthreads();

    for (int t = 0; t < TSTEPS; t++) {
        const int base  = t & (SLOTS - 1);
        const int s_in  = ((base + 3)  & (SLOTS - 1)) * HID;
        const int s_out = ((base + 62) & (SLOTS - 1)) * HID;

        float pf[NB];
#pragma unroll
        for (int b = 0; b < NB; b++) pf[b] = col[b][s_in];

        float wn[5];
#pragma unroll
        for (int k = 0; k < 5; k++) wn[k] = wtab[base * 5 + k];

        // ---- phase 2: rows rb..rb+7 x 4 batches over k-slice {32jj + 4s + e}
        //      jj=6,7 use register-resident W (instant-on after barrier) ----
        unsigned long long acc[8][4];
#pragma unroll
        for (int r = 0; r < 8; r++)
#pragma unroll
            for (int b = 0; b < 4; b++) acc[r][b] = 0ull;

#pragma unroll
        for (int jj = 6; jj < 8; jj++) {        // k in [192,256): W in registers
            const int off = jj * 32;
            ulonglong2 v0 = *(const ulonglong2*)(vbase + 0 * HID + off);
            ulonglong2 v1 = *(const ulonglong2*)(vbase + 1 * HID + off);
            ulonglong2 v2 = *(const ulonglong2*)(vbase + 2 * HID + off);
            ulonglong2 v3 = *(const ulonglong2*)(vbase + 3 * HID + off);
#pragma unroll
            for (int r = 0; r < 8; r++) {
                ulonglong2 w2 = wr[jj - 6][r];
                FFMA2(acc[r][0], w2.x, v0.x); FFMA2(acc[r][0], w2.y, v0.y);
                FFMA2(acc[r][1], w2.x, v1.x); FFMA2(acc[r][1], w2.y, v1.y);
                FFMA2(acc[r][2], w2.x, v2.x); FFMA2(acc[r][2], w2.y, v2.y);
                FFMA2(acc[r][3], w2.x, v3.x); FFMA2(acc[r][3], w2.y, v3.y);
            }
        }
#pragma unroll
        for (int jj = 0; jj < 6; jj++) {        // k in [0,192): W in SMEM
            const int off = jj * 32;
            ulonglong2 v0 = *(const ulonglong2*)(vbase + 0 * HID + off);
            ulonglong2 v1 = *(const ulonglong2*)(vbase + 1 * HID + off);
            ulonglong2 v2 = *(const ulonglong2*)(vbase + 2 * HID + off);
            ulonglong2 v3 = *(const ulonglong2*)(vbase + 3 * HID + off);
#pragma unroll
            for (int r = 0; r < 8; r++) {
                ulonglong2 w2 = *(const ulonglong2*)(wsm + r * KSM + off);
                FFMA2(acc[r][0], w2.x, v0.x); FFMA2(acc[r][0], w2.y, v0.y);
                FFMA2(acc[r][1], w2.x, v1.x); FFMA2(acc[r][1], w2.y, v1.y);
                FFMA2(acc[r][2], w2.x, v2.x); FFMA2(acc[r][2], w2.y, v2.y);
                FFMA2(acc[r][3], w2.x, v3.x); FFMA2(acc[r][3], w2.y, v3.y);
            }
        }

        // ---- unpack partials ----
        float P[8][4];
#pragma unroll
        for (int r = 0; r < 8; r++)
#pragma unroll
            for (int b = 0; b < 4; b++) {
                float lo = __uint_as_float((unsigned)(acc[r][b] & 0xffffffffu));
                float hi = __uint_as_float((unsigned)(acc[r][b] >> 32));
                P[r][b] = lo + hi;
            }

        // ---- next-step prep (independent; fills shuffle latency below) ----
        const int  tn = (t + 1) & (TSTEPS - 1);
        const int  basep = (t + 1) & (SLOTS - 1);
        const float Bc = fmaf(cs, stab[base], 1.0f);
        float wnp[5];
#pragma unroll
        for (int k = 0; k < 5; k++) wnp[k] = wtab[basep * 5 + k];
        float A[NB];
#pragma unroll
        for (int b = 0; b < NB; b++) {
            float pre = wnp[4] * pf[b];
#pragma unroll
            for (int k = 0; k < 4; k++) pre = fmaf(wnp[k], m[b][k + 1], pre);
            float embp = fast_tanh(fmaf(xsm[b * TSTEPS + tn], We_i, be_i));
            A[b] = fmaf(cs, pre, embp);
        }

        // ---- routed butterfly over 8 k-slices: lane ends with row rb+s ----
        const bool h4 = (s & 4), h2 = (s & 2), h1 = (s & 1);
        float Q[4][4];
#pragma unroll
        for (int r = 0; r < 4; r++)
#pragma unroll
            for (int b = 0; b < 4; b++) {
                float keep = h4 ? P[r + 4][b] : P[r][b];
                float send = h4 ? P[r][b]     : P[r + 4][b];
                Q[r][b] = keep + __shfl_xor_sync(0xffffffffu, send, 4);
            }
        float R2[2][4];
#pragma unroll
        for (int r = 0; r < 2; r++)
#pragma unroll
            for (int b = 0; b < 4; b++) {
                float keep = h2 ? Q[r + 2][b] : Q[r][b];
                float send = h2 ? Q[r][b]     : Q[r + 2][b];
                R2[r][b] = keep + __shfl_xor_sync(0xffffffffu, send, 2);
            }
        float hn[NB];
#pragma unroll
        for (int b = 0; b < 4; b++) {
            float keep = h1 ? R2[1][b] : R2[0][b];
            float send = h1 ? R2[0][b] : R2[1][b];
            float u = keep + __shfl_xor_sync(0xffffffffu, send, 1);
            hn[b] = fast_tanh(u + bu_i);
        }

        // ---- LayerNorm reductions: (sum, sumsq) x 4 batches ----
        float r8[8];
#pragma unroll
        for (int b = 0; b < NB; b++) { r8[b] = hn[b]; r8[4 + b] = hn[b] * hn[b]; }
#pragma unroll
        for (int o = 16; o > 0; o >>= 1)
#pragma unroll
            for (int q = 0; q < 8; q++)
                r8[q] += __shfl_xor_sync(0xffffffffu, r8[q], o);
        if (lane == 0) {
#pragma unroll
            for (int q = 0; q < 8; q++) red[warp * 8 + q] = r8[q];
        }
        __syncthreads();   // bar2: red visible; all vrow(t) reads complete

        float4 S1 = make_float4(0.f, 0.f, 0.f, 0.f);
        float4 S2 = make_float4(0.f, 0.f, 0.f, 0.f);
#pragma unroll
        for (int w = 0; w < 8; w++) {
            float4 a4 = *(const float4*)(red + w * 8);
            float4 c4 = *(const float4*)(red + w * 8 + 4);
            S1.x += a4.x; S1.y += a4.y; S1.z += a4.z; S1.w += a4.w;
            S2.x += c4.x; S2.y += c4.y; S2.z += c4.z; S2.w += c4.w;
        }
        float s1a[4] = {S1.x, S1.y, S1.z, S1.w};
        float s2a[4] = {S2.x, S2.y, S2.z, S2.w};

        // ---- critical tail: hb -> one FMA -> STS ----
        float hb[NB];
#pragma unroll
        for (int b = 0; b < NB; b++) {
            float mu  = s1a[b] * (1.0f / HID);
            float var = fmaf(s2a[b], 1.0f / HID, -mu * mu);
            hb[b] = (hn[b] - mu) * rsqrtf(var + EPSV) * g_i + bt_i;
            vrow[b * HID + i] = fmaf(Bc, hb[b], A[b]);   // v(t+1)
        }
        __syncthreads();   // bar1: vrow(t+1) visible for next phase-2

        // ---- off-path: slot flush + window shift ----
#pragma unroll
        for (int b = 0; b < NB; b++) {
            h[b] = hb[b];
            col[b][s_out] = fmaf(wn[0], hb[b], m[b][0]);
            m[b][0] = fmaf(wn[1], hb[b], m[b][1]);
            m[b][1] = fmaf(wn[2], hb[b], m[b][2]);
            m[b][2] = fmaf(wn[3], hb[b], m[b][3]);
            m[b][3] = fmaf(wn[4], hb[b], m[b][4]);
            m[b][4] = pf[b];
        }
    }

    // ---- output: out[b,:] = h[b] @ W_out^T + b_out ----
    __syncthreads();
#pragma unroll
    for (int b = 0; b < NB; b++) vrow[b * HID + i] = h[b];
    __syncthreads();
    if (tid < 160) {                       // 16 segments x 10 outputs
        int o = tid % 10, seg = tid / 10;
        float a0 = 0.f, a1 = 0.f, a2 = 0.f, a3 = 0.f;
#pragma unroll
        for (int jj = 0; jj < 16; jj++) {
            int ii = seg * 16 + jj;
            float w = W_out[o * HID + ii];
            a0 = fmaf(w, vrow[0 * HID + ii], a0);
            a1 = fmaf(w, vrow[1 * HID + ii], a1);
            a2 = fmaf(w, vrow[2 * HID + ii], a2);
            a3 = fmaf(w, vrow[3 * HID + ii], a3);
        }
        osm[tid * 4 + 0] = a0; osm[tid * 4 + 1] = a1;
        osm[tid * 4 + 2] = a2; osm[tid * 4 + 3] = a3;
    }
    __syncthreads();
    if (tid < NB * 10) {
        int o = tid % 10, b = tid / 10;
        float sum = b_out[o];
#pragma unroll
        for (int seg = 0; seg < 16; seg++)
            sum += osm[(seg * 10 + o) * 4 + b];
        out[(size_t)(b0 + b) * 10 + o] = sum;
    }
}

extern "C" void kernel_launch(void* const* d_in, const int* in_sizes, int n_in,
                              void* d_out, int out_size) {
    (void)in_sizes; (void)n_in; (void)out_size;
    const float* x        = (const float*)d_in[0];
    const float* W_embed  = (const float*)d_in[1];
    const float* b_embed  = (const float*)d_in[2];
    const float* W_update = (const float*)d_in[3];
    const float* b_update = (const float*)d_in[4];
    const float* gamma    = (const float*)d_in[5];
    const float* beta     = (const float*)d_in[6];
    const float* W_out    = (const float*)d_in[7];
    const float* b_out    = (const float*)d_in[8];
    const float* cs       = (const float*)d_in[9];

    const size_t SMEM_BYTES =
        (size_t)(HID * KSM + NB * HID + NB * TSTEPS + 320 + 64 + 64 + 640)
        * sizeof(float);   // 209,152 B

    cudaFuncSetAttribute(postnorm_rnn_kernel,
                         cudaFuncAttributeMaxDynamicSharedMemorySize,
                         (int)SMEM_BYTES);

    postnorm_rnn_kernel<<<BATCH / NB, NTH, SMEM_BYTES>>>(
        x, W_embed, b_embed, W_update, b_update, gamma, beta,
        W_out, b_out, cs, (float*)d_out);
}

// round 15
// speedup vs baseline: 1.3900x; 1.0751x over previous
#include <cuda_runtime.h>
#include <math.h>

#define HID     256
#define SLOTS   64
#define NB      4
#define TSTEPS  256
#define BATCH   512
#define KSM     160          // k-columns of W in SMEM; k in [160,256) in REGISTERS
#define NTH     256
#define EPSV    1e-5f

// Slot-memory scratch: 512 x 64 x 256 fp32 = 32 MB (L2-resident)
__device__ float g_mem[(size_t)BATCH * SLOTS * HID];

__device__ __forceinline__ float fast_tanh(float x) {
    float e = __expf(2.0f * x);
    return 1.0f - __fdividef(2.0f, e + 1.0f);
}

#define FFMA2(acc, a, b) \
    asm("fma.rn.f32x2 %0, %1, %2, %0;" : "+l"(acc) : "l"(a), "l"(b))

__global__ void __launch_bounds__(NTH, 1)
postnorm_rnn_kernel(const float* __restrict__ x,        // [512,256,1]
                    const float* __restrict__ W_embed,  // [256]
                    const float* __restrict__ b_embed,  // [256]
                    const float* __restrict__ W_update, // [256,256]
                    const float* __restrict__ b_update, // [256]
                    const float* __restrict__ gamma,    // [256]
                    const float* __restrict__ beta,     // [256]
                    const float* __restrict__ W_out,    // [10,256]
                    const float* __restrict__ b_out,    // [10]
                    const float* __restrict__ cs_in,    // [1]
                    float* __restrict__ out)            // [512,10]
{
    extern __shared__ float smem[];
    float* sW   = smem;                          // 256 rows x 160 cols = 40960 f
    float* vrow = sW + HID * KSM;                // [b][j] 4*256  =  1024 f
    float* xsm  = vrow + NB * HID;               // [b][t] 4*256  =  1024 f
    float* wtab = xsm + NB * TSTEPS;             // 64*5          =   320 f
    float* stab = wtab + 320;                    // 64 transition S values
    float* red  = stab + 64;                     // 8 warps x 8   =    64 f
    float* osm  = red + 64;                      // 160*4         =   640 f

    const int tid  = threadIdx.x;
    const int i    = tid;                 // hidden index owned (phase1/LN/mem)
    const int b0   = blockIdx.x * NB;
    const int warp = tid >> 5;
    const int lane = tid & 31;
    const int s    = tid & 7;             // k-slice id (8 slices of 32 k)
    const int rb   = tid & ~7;            // row block: rows rb..rb+7
    const int sK   = s * 4;               // k offset within each 32-float group

    // ---- zero this CTA's slot-memory slice ----
    {
        float4* mz = (float4*)(g_mem + (size_t)b0 * SLOTS * HID);
        for (int k = tid; k < NB * SLOTS * HID / 4; k += NTH)
            mz[k] = make_float4(0.f, 0.f, 0.f, 0.f);
    }
    // ---- stage W_update[:, 0:160] into SMEM (row-major, stride 160) ----
    {
        for (int idx = tid; idx < HID * (KSM / 4); idx += NTH) {
            int r = idx / (KSM / 4);           // 40 float4 per row
            int c = idx % (KSM / 4);
            ((float4*)(sW + r * KSM))[c] =
                ((const float4*)(W_update + (size_t)r * HID))[c];
        }
    }
    // ---- stage x: xsm[b][t] ----
    {
        int b = tid >> 6, t4 = tid & 63;
        ((float4*)xsm)[tid] =
            ((const float4*)(x + (size_t)(b0 + b) * TSTEPS))[t4];
    }
    // ---- precompute softmax weights + transition scalars S[base] ----
    if (tid < SLOTS) {
        int base = tid;
        float e[5], sum = 0.f, ep[5], sump = 0.f;
        int basep = (base + 1) & (SLOTS - 1);
#pragma unroll
        for (int k = 0; k < 5; k++) {
            int ix  = (base  + k - 2 + SLOTS) & (SLOTS - 1);
            int ixp = (basep + k - 2 + SLOTS) & (SLOTS - 1);
            float d  = (float)(ix  - base);
            float dp = (float)(ixp - basep);
            e[k]  = expf(-0.125f * d * d);   sum  += e[k];
            ep[k] = expf(-0.125f * dp * dp); sump += ep[k];
        }
        float inv = 1.0f / sum, invp = 1.0f / sump;
        float S = 0.f;
#pragma unroll
        for (int k = 0; k < 5; k++) {
            wtab[base * 5 + k] = e[k] * inv;
            if (k < 4) S += (ep[k] * invp) * (e[k + 1] * inv);
        }
        stab[base] = S;   // Sigma wn'(k) * wn(k+1), window-shift coupling
    }

    const float cs   = 1.0f / (1.0f + expf(-cs_in[0]));
    const float We_i = W_embed[i];
    const float be_i = b_embed[i];
    const float bu_i = b_update[i];
    const float g_i  = gamma[i];
    const float bt_i = beta[i];

    float h[NB];
    float m[NB][5];
    float* col[NB];
#pragma unroll
    for (int b = 0; b < NB; b++) {
        h[b] = 0.f;
        col[b] = g_mem + (size_t)(b0 + b) * SLOTS * HID + i;
#pragma unroll
        for (int k = 0; k < 5; k++) m[b][k] = 0.f;
    }

    // ---- hoist W k-tail (k in [160,256), jj=5,6,7) into REGISTERS, once ----
    ulonglong2 wr[3][8];
#pragma unroll
    for (int g = 0; g < 3; g++)
#pragma unroll
        for (int r = 0; r < 8; r++)
            wr[g][r] = __ldg((const ulonglong2*)
                (W_update + (size_t)(rb + r) * HID + (KSM + g * 32) + sK));

    const float* wsm   = sW + rb * KSM + sK;     // smem W, k<160
    const float* vbase = vrow + sK;

    __syncthreads();   // init visible

    // ---- vrow(0): ctx = 0, h = 0 -> v = tanh(x0*We+be) ----
#pragma unroll
    for (int b = 0; b < NB; b++)
        vrow[b * HID + i] = fast_tanh(fmaf(xsm[b * TSTEPS], We_i, be_i));
    __syncthreads();

    for (int t = 0; t < TSTEPS; t++) {
        const int base  = t & (SLOTS - 1);
        const int s_in  = ((base + 3)  & (SLOTS - 1)) * HID;
        const int s_out = ((base + 62) & (SLOTS - 1)) * HID;

        float pf[NB];
#pragma unroll
        for (int b = 0; b < NB; b++) pf[b] = col[b][s_in];

        float wn[5];
#pragma unroll
        for (int k = 0; k < 5; k++) wn[k] = wtab[base * 5 + k];

        // ---- phase 2: rows rb..rb+7 x 4 batches over k-slice {32jj + 4s + e}
        //      jj=5..7 use register-resident W (instant-on after barrier) ----
        unsigned long long acc[8][4];
#pragma unroll
        for (int r = 0; r < 8; r++)
#pragma unroll
            for (int b = 0; b < 4; b++) acc[r][b] = 0ull;

#pragma unroll
        for (int g = 0; g < 3; g++) {           // k in [160,256): W in registers
            const int off = KSM + g * 32;
            ulonglong2 v0 = *(const ulonglong2*)(vbase + 0 * HID + off);
            ulonglong2 v1 = *(const ulonglong2*)(vbase + 1 * HID + off);
            ulonglong2 v2 = *(const ulonglong2*)(vbase + 2 * HID + off);
            ulonglong2 v3 = *(const ulonglong2*)(vbase + 3 * HID + off);
#pragma unroll
            for (int r = 0; r < 8; r++) {
                ulonglong2 w2 = wr[g][r];
                FFMA2(acc[r][0], w2.x, v0.x); FFMA2(acc[r][0], w2.y, v0.y);
                FFMA2(acc[r][1], w2.x, v1.x); FFMA2(acc[r][1], w2.y, v1.y);
                FFMA2(acc[r][2], w2.x, v2.x); FFMA2(acc[r][2], w2.y, v2.y);
                FFMA2(acc[r][3], w2.x, v3.x); FFMA2(acc[r][3], w2.y, v3.y);
            }
        }
#pragma unroll
        for (int jj = 0; jj < 5; jj++) {        // k in [0,160): W in SMEM
            const int off = jj * 32;
            ulonglong2 v0 = *(const ulonglong2*)(vbase + 0 * HID + off);
            ulonglong2 v1 = *(const ulonglong2*)(vbase + 1 * HID + off);
            ulonglong2 v2 = *(const ulonglong2*)(vbase + 2 * HID + off);
            ulonglong2 v3 = *(const ulonglong2*)(vbase + 3 * HID + off);
#pragma unroll
            for (int r = 0; r < 8; r++) {
                ulonglong2 w2 = *(const ulonglong2*)(wsm + r * KSM + off);
                FFMA2(acc[r][0], w2.x, v0.x); FFMA2(acc[r][0], w2.y, v0.y);
                FFMA2(acc[r][1], w2.x, v1.x); FFMA2(acc[r][1], w2.y, v1.y);
                FFMA2(acc[r][2], w2.x, v2.x); FFMA2(acc[r][2], w2.y, v2.y);
                FFMA2(acc[r][3], w2.x, v3.x); FFMA2(acc[r][3], w2.y, v3.y);
            }
        }

        // ---- unpack partials ----
        float P[8][4];
#pragma unroll
        for (int r = 0; r < 8; r++)
#pragma unroll
            for (int b = 0; b < 4; b++) {
                float lo = __uint_as_float((unsigned)(acc[r][b] & 0xffffffffu));
                float hi = __uint_as_float((unsigned)(acc[r][b] >> 32));
                P[r][b] = lo + hi;
            }

        // ---- next-step prep (independent; fills shuffle latency below) ----
        const int  tn = (t + 1) & (TSTEPS - 1);
        const int  basep = (t + 1) & (SLOTS - 1);
        const float Bc = fmaf(cs, stab[base], 1.0f);
        float wnp[5];
#pragma unroll
        for (int k = 0; k < 5; k++) wnp[k] = wtab[basep * 5 + k];
        float A[NB];
#pragma unroll
        for (int b = 0; b < NB; b++) {
            float pre = wnp[4] * pf[b];
#pragma unroll
            for (int k = 0; k < 4; k++) pre = fmaf(wnp[k], m[b][k + 1], pre);
            float embp = fast_tanh(fmaf(xsm[b * TSTEPS + tn], We_i, be_i));
            A[b] = fmaf(cs, pre, embp);
        }

        // ---- routed butterfly over 8 k-slices: lane ends with row rb+s ----
        const bool h4 = (s & 4), h2 = (s & 2), h1 = (s & 1);
        float Q[4][4];
#pragma unroll
        for (int r = 0; r < 4; r++)
#pragma unroll
            for (int b = 0; b < 4; b++) {
                float keep = h4 ? P[r + 4][b] : P[r][b];
                float send = h4 ? P[r][b]     : P[r + 4][b];
                Q[r][b] = keep + __shfl_xor_sync(0xffffffffu, send, 4);
            }
        float R2[2][4];
#pragma unroll
        for (int r = 0; r < 2; r++)
#pragma unroll
            for (int b = 0; b < 4; b++) {
                float keep = h2 ? Q[r + 2][b] : Q[r][b];
                float send = h2 ? Q[r][b]     : Q[r + 2][b];
                R2[r][b] = keep + __shfl_xor_sync(0xffffffffu, send, 2);
            }
        float hn[NB];
#pragma unroll
        for (int b = 0; b < 4; b++) {
            float keep = h1 ? R2[1][b] : R2[0][b];
            float send = h1 ? R2[0][b] : R2[1][b];
            float u = keep + __shfl_xor_sync(0xffffffffu, send, 1);
            hn[b] = fast_tanh(u + bu_i);
        }

        // ---- LayerNorm: routed multi-value warp reduction (11 shfl) ----
        // quantities q: 0..3 = sum(hn[b]), 4..7 = sum(hn[b]^2)
        float r8[8];
#pragma unroll
        for (int b = 0; b < NB; b++) { r8[b] = hn[b]; r8[4 + b] = hn[b] * hn[b]; }
        const bool l1 = lane & 1, l2 = lane & 2, l4 = lane & 4;
        float a4v[4];
#pragma unroll
        for (int j = 0; j < 4; j++) {          // route on q bit0
            float keep = l1 ? r8[2 * j + 1] : r8[2 * j];
            float send = l1 ? r8[2 * j]     : r8[2 * j + 1];
            a4v[j] = keep + __shfl_xor_sync(0xffffffffu, send, 1);
        }
        float b2v[2];
#pragma unroll
        for (int j = 0; j < 2; j++) {          // route on q bit1
            float keep = l2 ? a4v[2 * j + 1] : a4v[2 * j];
            float send = l2 ? a4v[2 * j]     : a4v[2 * j + 1];
            b2v[j] = keep + __shfl_xor_sync(0xffffffffu, send, 2);
        }
        float c1;
        {                                      // route on q bit2
            float keep = l4 ? b2v[1] : b2v[0];
            float send = l4 ? b2v[0] : b2v[1];
            c1 = keep + __shfl_xor_sync(0xffffffffu, send, 4);
        }
        c1 += __shfl_xor_sync(0xffffffffu, c1, 8);
        c1 += __shfl_xor_sync(0xffffffffu, c1, 16);
        if (lane < 8) red[warp * 8 + lane] = c1;   // q == lane
        __syncthreads();   // bar2: red visible; all vrow(t) reads complete

        float4 S1 = make_float4(0.f, 0.f, 0.f, 0.f);
        float4 S2 = make_float4(0.f, 0.f, 0.f, 0.f);
#pragma unroll
        for (int w = 0; w < 8; w++) {
            float4 a4 = *(const float4*)(red + w * 8);
            float4 c4 = *(const float4*)(red + w * 8 + 4);
            S1.x += a4.x; S1.y += a4.y; S1.z += a4.z; S1.w += a4.w;
            S2.x += c4.x; S2.y += c4.y; S2.z += c4.z; S2.w += c4.w;
        }
        float s1a[4] = {S1.x, S1.y, S1.z, S1.w};
        float s2a[4] = {S2.x, S2.y, S2.z, S2.w};

        // ---- critical tail: hb -> one FMA -> STS ----
        float hb[NB];
#pragma unroll
        for (int b = 0; b < NB; b++) {
            float mu  = s1a[b] * (1.0f / HID);
            float var = fmaf(s2a[b], 1.0f / HID, -mu * mu);
            hb[b] = (hn[b] - mu) * rsqrtf(var + EPSV) * g_i + bt_i;
            vrow[b * HID + i] = fmaf(Bc, hb[b], A[b]);   // v(t+1)
        }
        __syncthreads();   // bar1: vrow(t+1) visible for next phase-2

        // ---- off-path: slot flush + window shift ----
#pragma unroll
        for (int b = 0; b < NB; b++) {
            h[b] = hb[b];
            col[b][s_out] = fmaf(wn[0], hb[b], m[b][0]);
            m[b][0] = fmaf(wn[1], hb[b], m[b][1]);
            m[b][1] = fmaf(wn[2], hb[b], m[b][2]);
            m[b][2] = fmaf(wn[3], hb[b], m[b][3]);
            m[b][3] = fmaf(wn[4], hb[b], m[b][4]);
            m[b][4] = pf[b];
        }
    }

    // ---- output: out[b,:] = h[b] @ W_out^T + b_out ----
    __syncthreads();
#pragma unroll
    for (int b = 0; b < NB; b++) vrow[b * HID + i] = h[b];
    __syncthreads();
    if (tid < 160) {                       // 16 segments x 10 outputs
        int o = tid % 10, seg = tid / 10;
        float a0 = 0.f, a1 = 0.f, a2 = 0.f, a3 = 0.f;
#pragma unroll
        for (int jj = 0; jj < 16; jj++) {
            int ii = seg * 16 + jj;
            float w = W_out[o * HID + ii];
            a0 = fmaf(w, vrow[0 * HID + ii], a0);
            a1 = fmaf(w, vrow[1 * HID + ii], a1);
            a2 = fmaf(w, vrow[2 * HID + ii], a2);
            a3 = fmaf(w, vrow[3 * HID + ii], a3);
        }
        osm[tid * 4 + 0] = a0; osm[tid * 4 + 1] = a1;
        osm[tid * 4 + 2] = a2; osm[tid * 4 + 3] = a3;
    }
    __syncthreads();
    if (tid < NB * 10) {
        int o = tid % 10, b = tid / 10;
        float sum = b_out[o];
#pragma unroll
        for (int seg = 0; seg < 16; seg++)
            sum += osm[(seg * 10 + o) * 4 + b];
        out[(size_t)(b0 + b) * 10 + o] = sum;
    }
}

extern "C" void kernel_launch(void* const* d_in, const int* in_sizes, int n_in,
                              void* d_out, int out_size) {
    (void)in_sizes; (void)n_in; (void)out_size;
    const float* x        = (const float*)d_in[0];
    const float* W_embed  = (const float*)d_in[1];
    const float* b_embed  = (const float*)d_in[2];
    const float* W_update = (const float*)d_in[3];
    const float* b_update = (const float*)d_in[4];
    const float* gamma    = (const float*)d_in[5];
    const float* beta     = (const float*)d_in[6];
    const float* W_out    = (const float*)d_in[7];
    const float* b_out    = (const float*)d_in[8];
    const float* cs       = (const float*)d_in[9];

    const size_t SMEM_BYTES =
        (size_t)(HID * KSM + NB * HID + NB * TSTEPS + 320 + 64 + 64 + 640)
        * sizeof(float);   // 176,448 B

    cudaFuncSetAttribute(postnorm_rnn_kernel,
                         cudaFuncAttributeMaxDynamicSharedMemorySize,
                         (int)SMEM_BYTES);

    postnorm_rnn_kernel<<<BATCH / NB, NTH, SMEM_BYTES>>>(
        x, W_embed, b_embed, W_update, b_update, gamma, beta,
        W_out, b_out, cs, (float*)d_out);
}